// round 10
// baseline (speedup 1.0000x reference)
#include <cuda_runtime.h>
#include <cstdint>

// ShoeboxToRIR — round 10: single kernel, grid 256, one wave.
// 384 threads = 3 sub-blocks of 128; each sub-block owns a private padded
// smem RIR copy and processes 1/3 of the 1561 images (521). Thread t owns
// samples == t (mod 128); window 81 < 128 -> at most one tap per image per
// thread (race-free, deterministic). smem 111.6 KB -> 2 CTAs/SM, 256 CTAs
// resident in ONE wave (no combine kernel, no scratch, no clusters).
// Phase-1 fast-math: rsqrt (kills divide), __expf pow, __float2int_ru,
// blended __sinf/Taylor for sin(pi*frac) with relative accuracy at tiny frac.

#define NIMG    1561
#define NBATCH  256
#define RIRLEN  8000
#define NS      3
#define NTH     (NS * 128)
#define CHUNK   521          // ceil(1561/3)
#define COPYLEN 8256         // 48 lower pad + 8000 + 208 upper pad (floats)
#define LOWPAD  48
#define PADK    40

struct GTab { int v[NIMG]; };
static constexpr int cabs_(int x) { return x < 0 ? -x : x; }
static constexpr GTab make_gtab() {
    GTab g{}; int s = 0;
    for (int x = -10; x <= 10; ++x)
        for (int y = -10; y <= 10; ++y)
            for (int z = -10; z <= 10; ++z) {
                int E = cabs_(x) + cabs_(y) + cabs_(z);
                if (E <= 10)
                    g.v[s++] = (x + 10) | ((y + 10) << 5) | ((z + 10) << 10) | (E << 15);
            }
    return g;
}
__device__ constexpr GTab G = make_gtab();

__global__ __launch_bounds__(NTH, 2)
void rir_kernel(const float* __restrict__ in, float* __restrict__ out, int write_toa)
{
    extern __shared__ float smem[];
    float*  rir_s  = smem;                           // NS * COPYLEN
    float4* params = (float4*)(smem + NS * COPYLEN); // NIMG float4

    const int b   = blockIdx.x;
    const int tid = threadIdx.x;
    const int sub = tid >> 7;
    const int t   = tid & 127;

    // zero private copies (16B vectorized)
    {
        float4* z = (float4*)rir_s;
        for (int p = tid; p < NS * COPYLEN / 4; p += NTH)
            z[p] = make_float4(0.f, 0.f, 0.f, 0.f);
    }

    // ---- phase 1: per-image parameters ----
    const float* ip = in + b * 10;
    const float rx = ip[0], ry = ip[1], rz = ip[2];
    const float mx = ip[3] * rx, my = ip[4] * ry, mz = ip[5] * rz;
    const float sx = ip[6] * rx, sy = ip[7] * ry, sz = ip[8] * rz;
    const float ltr = __logf(sqrtf(1.0f - ip[9]));   // ln(tr), once per thread
    const float PI_F = 3.14159265358979323846f;

    for (int sl = tid; sl < NIMG; sl += NTH) {
        const int pk = G.v[sl];
        const int gx = (pk & 31) - 10;
        const int gy = ((pk >> 5) & 31) - 10;
        const int gz = ((pk >> 10) & 31) - 10;
        const int E  = pk >> 15;

        const float ix = (gx & 1) ? (rx * (float)(gx + 1) - sx) : (rx * (float)gx + sx);
        const float iy = (gy & 1) ? (ry * (float)(gy + 1) - sy) : (ry * (float)gy + sy);
        const float iz = (gz & 1) ? (rz * (float)(gz + 1) - sz) : (rz * (float)gz + sz);

        const float dx = ix - mx, dy = iy - my, dz = iz - mz;
        const float d2   = dx * dx + dy * dy + dz * dz;
        const float rinv = rsqrtf(d2);               // MUFU.RSQ
        const float dist = d2 * rinv;

        const float att = __expf((float)E * ltr);    // tr^E, MUFU.EX2 path
        const float amp = att * rinv;                // att/dist, no divide

        const float delay = dist * (16000.0f / 343.0f);
        const int   dii   = __float2int_ru(delay);   // ceil
        const float di    = (float)dii;              // exact (< 2^24)
        float frac = fmaxf(di - delay, 1e-9f);       // exact Sterbenz; clamp kills x==0

        // sin(pi*frac) with RELATIVE accuracy everywhere:
        const float pf = PI_F * frac;
        const float s_tay  = pf * fmaf(pf * pf, -(1.0f / 6.0f), 1.0f); // tiny-frac path
        const float s_fast = __sinf(pf);                               // frac >= 0.01
        const float s = (frac < 0.01f) ? s_tay : s_fast;

        int a = dii - PADK;
        float q = ((dii & 1) ? -amp : amp) * s * (1.0f / PI_F);
        if (a >= RIRLEN) { a = RIRLEN; q = 0.0f; }   // zero taps land in upper pad

        params[sl] = make_float4(q, frac, __int_as_float(a * 4), 0.0f);
    }

    if (tid == 0 && write_toa) {
        const float ddx = mx - sx, ddy = my - sy, ddz = mz - sz;
        out[NBATCH * RIRLEN + b] =
            40.0f + sqrtf(ddx * ddx + ddy * ddy + ddz * ddz) * (16000.0f / 343.0f);
    }
    __syncthreads();

    // ---- phase 2: single-predicate byte-space accumulation ----
    const int i0 = sub * CHUNK;
    const int i1 = (i0 + CHUNK < NIMG) ? (i0 + CHUNK) : NIMG;
    char* myrir_b = (char*)(rir_s + sub * COPYLEN + LOWPAD);
    const int t4 = t * 4;
    const float PI40 = 0.07853981633974483f;

    #pragma unroll 4
    for (int i = i0; i < i1; ++i) {
        const float4 p = params[i];                   // broadcast LDS.128
        const int a4 = __float_as_int(p.z);
        const int jb = (t4 - a4) & 508;               // 4*j, j = (t-a) mod 128
        const float x  = fmaf((float)jb, 0.25f, -40.0f) + p.y;  // (j-40)+frac, never 0
        const float hv = 0.5f + 0.5f * __cosf(x * PI40);        // hann
        const float v  = __fdividef(p.x, x) * hv;               // q/x * hann
        if (jb < 320) {                               // j < 80 (predicated RMW)
            float* ap = (float*)(myrir_b + a4 + jb);
            *ap += v;
        }
    }
    __syncthreads();

    // ---- phase 3: reduce 3 copies, apply (-1)^pos, write (float4 STG) ----
    {
        const float4* c0 = (const float4*)(rir_s + LOWPAD);
        const float4* c1 = (const float4*)(rir_s + COPYLEN + LOWPAD);
        const float4* c2 = (const float4*)(rir_s + 2 * COPYLEN + LOWPAD);
        float4* orow = (float4*)(out + (size_t)b * RIRLEN);
        for (int i = tid; i < RIRLEN / 4; i += NTH) {
            float4 a = c0[i], u = c1[i], w = c2[i];
            float4 r;
            r.x =  (a.x + u.x + w.x);
            r.y = -(a.y + u.y + w.y);
            r.z =  (a.z + u.z + w.z);
            r.w = -(a.w + u.w + w.w);
            orow[i] = r;
        }
    }
}

extern "C" void kernel_launch(void* const* d_in, const int* in_sizes, int n_in,
                              void* d_out, int out_size)
{
    const float* in  = (const float*)d_in[0];
    float*       out = (float*)d_out;
    const int write_toa = (out_size >= NBATCH * RIRLEN + NBATCH) ? 1 : 0;

    const int smem_bytes = NS * COPYLEN * 4 + NIMG * 16;   // 99072 + 24976 = 124048
    cudaFuncSetAttribute(rir_kernel,
                         cudaFuncAttributeMaxDynamicSharedMemorySize, smem_bytes);

    rir_kernel<<<NBATCH, NTH, smem_bytes>>>(in, out, write_toa);
}

// round 12
// speedup vs baseline: 1.2131x; 1.2131x over previous
#include <cuda_runtime.h>
#include <cstdint>

// ShoeboxToRIR — round 11: single kernel, grid 256, ONE wave at 2 CTAs/SM.
// 384 threads = 3 sub-blocks of 128; each sub-block owns a private padded
// smem RIR copy (8120 floats) and processes 1/3 of the 1561 images (521).
// Thread t owns samples == t (mod 128); window 81 < 128 -> at most one tap
// per image per thread (race-free, deterministic).
// Smem diet vs round 10 (which fell to 1 CTA/SM): COPYLEN 8256->8120,
// params split into float2(q,frac) + int16(a*4)  => 113.1 KB -> 2 CTAs/SM.

#define NIMG    1561
#define NBATCH  256
#define RIRLEN  8000
#define NS      3
#define NTH     (NS * 128)
#define CHUNK   521          // ceil(1561/3)
#define COPYLEN 8120         // 40 lower pad + 8080 (pos up to 8079)
#define LOWPAD  40
#define PADK    40

struct GTab { int v[NIMG]; };
static constexpr int cabs_(int x) { return x < 0 ? -x : x; }
static constexpr GTab make_gtab() {
    GTab g{}; int s = 0;
    for (int x = -10; x <= 10; ++x)
        for (int y = -10; y <= 10; ++y)
            for (int z = -10; z <= 10; ++z) {
                int E = cabs_(x) + cabs_(y) + cabs_(z);
                if (E <= 10)
                    g.v[s++] = (x + 10) | ((y + 10) << 5) | ((z + 10) << 10) | (E << 15);
            }
    return g;
}
__device__ constexpr GTab G = make_gtab();

__global__ __launch_bounds__(NTH, 2)
void rir_kernel(const float* __restrict__ in, float* __restrict__ out, int write_toa)
{
    extern __shared__ float smem[];
    float*  rir_s  = smem;                                   // NS*COPYLEN floats
    float2* params = (float2*)(smem + NS * COPYLEN);         // NIMG float2 (q, frac)
    short*  a16    = (short*)((char*)smem + NS * COPYLEN * 4 + NIMG * 8); // NIMG s16 (a*4)

    const int b   = blockIdx.x;
    const int tid = threadIdx.x;
    const int sub = tid >> 7;
    const int t   = tid & 127;

    // zero private copies (16B vectorized; NS*COPYLEN divisible by 4)
    {
        float4* z = (float4*)rir_s;
        for (int p = tid; p < NS * COPYLEN / 4; p += NTH)
            z[p] = make_float4(0.f, 0.f, 0.f, 0.f);
    }

    // ---- phase 1: per-image parameters ----
    const float* ip = in + b * 10;
    const float rx = ip[0], ry = ip[1], rz = ip[2];
    const float mx = ip[3] * rx, my = ip[4] * ry, mz = ip[5] * rz;
    const float sx = ip[6] * rx, sy = ip[7] * ry, sz = ip[8] * rz;
    const float ltr = __logf(sqrtf(1.0f - ip[9]));   // ln(tr)
    const float PI_F = 3.14159265358979323846f;

    for (int sl = tid; sl < NIMG; sl += NTH) {
        const int pk = G.v[sl];
        const int gx = (pk & 31) - 10;
        const int gy = ((pk >> 5) & 31) - 10;
        const int gz = ((pk >> 10) & 31) - 10;
        const int E  = pk >> 15;

        const float ix = (gx & 1) ? (rx * (float)(gx + 1) - sx) : (rx * (float)gx + sx);
        const float iy = (gy & 1) ? (ry * (float)(gy + 1) - sy) : (ry * (float)gy + sy);
        const float iz = (gz & 1) ? (rz * (float)(gz + 1) - sz) : (rz * (float)gz + sz);

        const float dx = ix - mx, dy = iy - my, dz = iz - mz;
        const float d2   = dx * dx + dy * dy + dz * dz;
        const float rinv = rsqrtf(d2);               // MUFU.RSQ
        const float dist = d2 * rinv;

        const float att = __expf((float)E * ltr);    // tr^E
        const float amp = att * rinv;                // att/dist, no divide

        const float delay = dist * (16000.0f / 343.0f);
        const int   dii   = __float2int_ru(delay);   // ceil
        const float di    = (float)dii;              // exact (< 2^24)
        float frac = fmaxf(di - delay, 1e-9f);       // exact Sterbenz; clamp kills x==0

        // sin(pi*frac) with relative accuracy everywhere
        const float pf = PI_F * frac;
        const float s_tay  = pf * fmaf(pf * pf, -(1.0f / 6.0f), 1.0f);
        const float s_fast = __sinf(pf);
        const float s = (frac < 0.01f) ? s_tay : s_fast;

        int a = dii - PADK;                          // in [-39, ...]
        float q = ((dii & 1) ? -amp : amp) * s * (1.0f / PI_F);
        if (a >= RIRLEN) { a = RIRLEN; q = 0.0f; }   // zero taps -> pad region

        params[sl] = make_float2(q, frac);
        a16[sl]    = (short)(a * 4);                 // fits s16: [-156, 32000]
    }

    if (tid == 0 && write_toa) {
        const float ddx = mx - sx, ddy = my - sy, ddz = mz - sz;
        out[NBATCH * RIRLEN + b] =
            40.0f + sqrtf(ddx * ddx + ddy * ddy + ddz * ddz) * (16000.0f / 343.0f);
    }
    __syncthreads();

    // ---- phase 2: single-predicate byte-space accumulation ----
    const int i0 = sub * CHUNK;
    const int i1 = (i0 + CHUNK < NIMG) ? (i0 + CHUNK) : NIMG;
    char* myrir_b = (char*)(rir_s + sub * COPYLEN + LOWPAD);
    const int t4 = t * 4;
    const float PI40 = 0.07853981633974483f;

    #pragma unroll 4
    for (int i = i0; i < i1; ++i) {
        const float2 p  = params[i];                  // broadcast LDS.64 (q, frac)
        const int    a4 = a16[i];                     // broadcast LDS.S16
        const int jb = (t4 - a4) & 508;               // 4*j, j = (t-a) mod 128
        const float x  = fmaf((float)jb, 0.25f, -40.0f) + p.y;  // (j-40)+frac, never 0
        const float hv = 0.5f + 0.5f * __cosf(x * PI40);        // hann
        const float v  = __fdividef(p.x, x) * hv;               // q/x * hann
        if (jb < 320) {                               // j < 80 (predicated RMW)
            float* ap = (float*)(myrir_b + a4 + jb);
            *ap += v;
        }
    }
    __syncthreads();

    // ---- phase 3: reduce 3 copies, apply (-1)^pos, write (float4 STG) ----
    {
        const float4* c0 = (const float4*)(rir_s + LOWPAD);
        const float4* c1 = (const float4*)(rir_s + COPYLEN + LOWPAD);
        const float4* c2 = (const float4*)(rir_s + 2 * COPYLEN + LOWPAD);
        float4* orow = (float4*)(out + (size_t)b * RIRLEN);
        for (int i = tid; i < RIRLEN / 4; i += NTH) {
            float4 a = c0[i], u = c1[i], w = c2[i];
            float4 r;
            r.x =  (a.x + u.x + w.x);
            r.y = -(a.y + u.y + w.y);
            r.z =  (a.z + u.z + w.z);
            r.w = -(a.w + u.w + w.w);
            orow[i] = r;
        }
    }
}

extern "C" void kernel_launch(void* const* d_in, const int* in_sizes, int n_in,
                              void* d_out, int out_size)
{
    const float* in  = (const float*)d_in[0];
    float*       out = (float*)d_out;
    const int write_toa = (out_size >= NBATCH * RIRLEN + NBATCH) ? 1 : 0;

    // 3*8120*4 + 1561*8 + 1561*2  = 97440 + 12488 + 3122 = 113050 -> pad to 16
    const int smem_bytes = (NS * COPYLEN * 4 + NIMG * 8 + NIMG * 2 + 15) & ~15;
    cudaFuncSetAttribute(rir_kernel,
                         cudaFuncAttributeMaxDynamicSharedMemorySize, smem_bytes);

    rir_kernel<<<NBATCH, NTH, smem_bytes>>>(in, out, write_toa);
}